// round 4
// baseline (speedup 1.0000x reference)
#include <cuda_runtime.h>

#define NMAX 5000000

// Scratch (__device__ globals only — no allocation allowed)
__device__ float g_deg[NMAX];   // in-degree incl. self loop
__device__ float g_xwd[NMAX];   // x*w*rsqrt(deg)
__device__ float g_s[NMAX];     // sum over incoming edges of xwd[src]
__device__ int   g_is64;        // 1 if edge_index is int64 on device

// ---------------------------------------------------------------------------
// Probe: int64 node indices (< 2^32) have zero high words at odd positions.
__global__ void k_detect(const unsigned int* __restrict__ e, int n) {
    if (blockIdx.x == 0 && threadIdx.x == 0) {
        int is64 = 1;
        #pragma unroll 1
        for (int i = 0; i < 64; i++) {
            unsigned lo = e[2 * i];
            unsigned hi = e[2 * i + 1];
            if (hi != 0u || lo >= (unsigned)n) { is64 = 0; break; }
        }
        g_is64 = is64;
    }
}

// K0: init deg=1 (self loop), s=0
__global__ void k_init(int n) {
    int i = blockIdx.x * blockDim.x + threadIdx.x;
    if (i < n) { g_deg[i] = 1.0f; g_s[i] = 0.0f; }
}

// K1: degree count over edge targets. 4 edges/thread, vectorized index loads.
__global__ void k_deg(const void* __restrict__ ei, long long ne) {
    int is64 = g_is64;
    long long q = ne >> 2;                       // number of 4-edge groups
    long long stride = (long long)gridDim.x * blockDim.x;
    long long t0 = (long long)blockIdx.x * blockDim.x + threadIdx.x;

    if (is64) {
        const longlong2* col2 = (const longlong2*)((const long long*)ei + ne);
        for (long long g = t0; g < q; g += stride) {
            longlong2 a = col2[2 * g];
            longlong2 b = col2[2 * g + 1];
            atomicAdd(&g_deg[(int)a.x], 1.0f);
            atomicAdd(&g_deg[(int)a.y], 1.0f);
            atomicAdd(&g_deg[(int)b.x], 1.0f);
            atomicAdd(&g_deg[(int)b.y], 1.0f);
        }
        // tail
        const long long* col = (const long long*)ei + ne;
        for (long long i = 4 * q + t0; i < ne; i += stride)
            atomicAdd(&g_deg[(int)col[i]], 1.0f);
    } else {
        const int4* col4 = (const int4*)((const int*)ei + ne);
        for (long long g = t0; g < q; g += stride) {
            int4 c = col4[g];
            atomicAdd(&g_deg[c.x], 1.0f);
            atomicAdd(&g_deg[c.y], 1.0f);
            atomicAdd(&g_deg[c.z], 1.0f);
            atomicAdd(&g_deg[c.w], 1.0f);
        }
        const int* col = (const int*)ei + ne;
        for (long long i = 4 * q + t0; i < ne; i += stride)
            atomicAdd(&g_deg[col[i]], 1.0f);
    }
}

// K2: xwd[i] = x[i]*w*rsqrt(deg[i])
__global__ void k_prep(const float* __restrict__ x, const float* __restrict__ conv_w, int n) {
    int i = blockIdx.x * blockDim.x + threadIdx.x;
    if (i < n) {
        g_xwd[i] = x[i] * conv_w[0] * rsqrtf(g_deg[i]);
    }
}

// K3: s[col] += xwd[row]. 4 edges/thread, vectorized index loads.
__global__ void k_scatter(const void* __restrict__ ei, long long ne) {
    int is64 = g_is64;
    long long q = ne >> 2;
    long long stride = (long long)gridDim.x * blockDim.x;
    long long t0 = (long long)blockIdx.x * blockDim.x + threadIdx.x;

    if (is64) {
        const longlong2* row2 = (const longlong2*)((const long long*)ei);
        const longlong2* col2 = (const longlong2*)((const long long*)ei + ne);
        for (long long g = t0; g < q; g += stride) {
            longlong2 ra = row2[2 * g], rb = row2[2 * g + 1];
            longlong2 ca = col2[2 * g], cb = col2[2 * g + 1];
            float v0 = g_xwd[(int)ra.x];
            float v1 = g_xwd[(int)ra.y];
            float v2 = g_xwd[(int)rb.x];
            float v3 = g_xwd[(int)rb.y];
            atomicAdd(&g_s[(int)ca.x], v0);
            atomicAdd(&g_s[(int)ca.y], v1);
            atomicAdd(&g_s[(int)cb.x], v2);
            atomicAdd(&g_s[(int)cb.y], v3);
        }
        const long long* row = (const long long*)ei;
        const long long* col = (const long long*)ei + ne;
        for (long long i = 4 * q + t0; i < ne; i += stride)
            atomicAdd(&g_s[(int)col[i]], g_xwd[(int)row[i]]);
    } else {
        const int4* row4 = (const int4*)((const int*)ei);
        const int4* col4 = (const int4*)((const int*)ei + ne);
        for (long long g = t0; g < q; g += stride) {
            int4 r = row4[g];
            int4 c = col4[g];
            float v0 = g_xwd[r.x];
            float v1 = g_xwd[r.y];
            float v2 = g_xwd[r.z];
            float v3 = g_xwd[r.w];
            atomicAdd(&g_s[c.x], v0);
            atomicAdd(&g_s[c.y], v1);
            atomicAdd(&g_s[c.z], v2);
            atomicAdd(&g_s[c.w], v3);
        }
        const int* row = (const int*)ei;
        const int* col = (const int*)ei + ne;
        for (long long i = 4 * q + t0; i < ne; i += stride)
            atomicAdd(&g_s[col[i]], g_xwd[row[i]]);
    }
}

// K4: per-graph FC readout. One warp per graph (50 nodes).
__global__ void k_final(const float* __restrict__ conv_b,
                        const float* __restrict__ fc_w,
                        const float* __restrict__ fc_b,
                        float* __restrict__ out, int ngraphs) {
    int gwarp = (blockIdx.x * blockDim.x + threadIdx.x) >> 5;
    int lane = threadIdx.x & 31;
    if (gwarp >= ngraphs) return;
    float b = conv_b[0];
    float p0 = 0.0f, p1 = 0.0f;
    int base = gwarp * 50;
    for (int j = lane; j < 50; j += 32) {
        int idx = base + j;
        float dis = rsqrtf(g_deg[idx]);
        float h = dis * (g_s[idx] + g_xwd[idx]) + b;
        p0 = fmaf(h, fc_w[j],      p0);
        p1 = fmaf(h, fc_w[50 + j], p1);
    }
    #pragma unroll
    for (int off = 16; off; off >>= 1) {
        p0 += __shfl_xor_sync(0xffffffffu, p0, off);
        p1 += __shfl_xor_sync(0xffffffffu, p1, off);
    }
    if (lane == 0) {
        out[gwarp * 2 + 0] = p0 + fc_b[0];
        out[gwarp * 2 + 1] = p1 + fc_b[1];
    }
}

// ---------------------------------------------------------------------------
extern "C" void kernel_launch(void* const* d_in, const int* in_sizes, int n_in,
                              void* d_out, int out_size) {
    const float* x      = (const float*)d_in[0];   // [N,1] f32
    const void*  ei     = d_in[1];                 // [2,E] int32 or int64
    const float* conv_w = (const float*)d_in[2];   // [1,1]
    const float* conv_b = (const float*)d_in[3];   // [1]
    const float* fc_w   = (const float*)d_in[4];   // [2,50]
    const float* fc_b   = (const float*)d_in[5];   // [2]
    float*       out    = (float*)d_out;           // [G,2]

    int       n  = in_sizes[0];                    // 5,000,000 nodes
    long long ne = (long long)in_sizes[1] / 2;     // 80,000,000 edges
    int       ng = out_size / 2;                   // 100,000 graphs

    const int T = 256;
    int edge_blocks = 148 * 16;   // grid-stride; ~606k threads

    k_detect<<<1, 32>>>((const unsigned int*)ei, n);
    k_init<<<(n + T - 1) / T, T>>>(n);
    k_deg<<<edge_blocks, T>>>(ei, ne);
    k_prep<<<(n + T - 1) / T, T>>>(x, conv_w, n);
    k_scatter<<<edge_blocks, T>>>(ei, ne);

    long long fin_threads = (long long)ng * 32;
    k_final<<<(unsigned)((fin_threads + T - 1) / T), T>>>(conv_b, fc_w, fc_b, out, ng);
}